// round 8
// baseline (speedup 1.0000x reference)
#include <cuda_runtime.h>

// LSTM_Univariate: T=32768 timesteps, F=512 independent scalar LSTM cells.
// One thread per feature; serial recurrence over T with a minimized
// per-iteration dependency chain (~100 cyc). Sigmoid/tanh via
// ex2.approx + rcp.approx (1-2 ulp) with log2(e) pre-folded into weights.

#define TT 32768
#define FF 512
#define PD 8   // x prefetch depth (register ring)

__device__ __forceinline__ float ex2f_(float x) {
    float y; asm("ex2.approx.f32 %0, %1;" : "=f"(y) : "f"(x)); return y;
}
__device__ __forceinline__ float rcpf_(float x) {
    float y; asm("rcp.approx.f32 %0, %1;" : "=f"(y) : "f"(x)); return y;
}

__global__ void __launch_bounds__(128, 1)
lstm_uni_kernel(const float*  __restrict__ x,
                const float4* __restrict__ wih,
                const float4* __restrict__ whh,
                const float4* __restrict__ bih,
                const float4* __restrict__ bhh,
                const float*  __restrict__ h0,
                const float*  __restrict__ c0,
                float*        __restrict__ out)
{
    const int f = blockIdx.x * blockDim.x + threadIdx.x;  // feature id, 0..511

    const float L  = 1.4426950408889634f;   // log2(e)
    const float K  = -2.0f * L;             // scale for tanh args
    const float K2 = 2.0f * K;

    // PyTorch gate order in columns: [i, f, g, o] -> .x .y .z .w
    const float4 wi = wih[f];
    const float4 wh = whh[f];
    const float4 bi = bih[f];
    const float4 bh = bhh[f];

    // sigmoid(z) = rcp(1 + ex2(-L*z));  tanh(z) = 2*rcp(1 + ex2(-2L*z)) - 1.
    // Fold the -L / -2L scales into the per-gate weights & biases.
    const float wii = -L * wi.x,        whi = -L * wh.x,        bii = -L * (bi.x + bh.x);
    const float wff = -L * wi.y,        whf = -L * wh.y,        bff = -L * (bi.y + bh.y);
    const float wgg = -2.0f * L * wi.z, whg = -2.0f * L * wh.z, bgg = -2.0f * L * (bi.z + bh.z);
    const float woo = -L * wi.w,        who = -L * wh.w,        boo = -L * (bi.w + bh.w);

    float h  = h0[f];
    float c  = c0[f];
    float cs = K * c;   // carried pre-scaled cell state: cs == K*c (same recurrence)

    // Prefetch ring: x for iteration t+PD is loaded at iteration t.
    float xb[PD];
#pragma unroll
    for (int j = 0; j < PD; ++j) xb[j] = x[j * FF + f];

    const float* xp = x + f;
    float*       op = out + f;

    for (int t = 0; t < TT; t += PD) {
#pragma unroll
        for (int j = 0; j < PD; ++j) {
            const float xt = xb[j];
            const int tp = t + j + PD;
            if (tp < TT) xb[j] = xp[tp * FF];          // predicated prefetch (off-chain)

            // pre-activations (off the recurrence chain: xt ready PD iters ago)
            const float pi = fmaf(xt, wii, bii);
            const float pf = fmaf(xt, wff, bff);
            const float pg = fmaf(xt, wgg, bgg);
            const float po = fmaf(xt, woo, boo);

            // chain: 1 FFMA to form each (scaled) gate argument
            const float ai = fmaf(h, whi, pi);
            const float af = fmaf(h, whf, pf);
            const float ag = fmaf(h, whg, pg);
            const float ao = fmaf(h, who, po);

            // gate nonlinearities: EX2 -> +1 -> RCP
            const float gi = rcpf_(1.0f + ex2f_(ai));   // i = sigmoid(gate_i)
            const float gf = rcpf_(1.0f + ex2f_(af));   // f = sigmoid(gate_f)
            const float sg = rcpf_(1.0f + ex2f_(ag));   // sigm(2*gate_g); g = 2*sg - 1
            const float go = rcpf_(1.0f + ex2f_(ao));   // o = sigmoid(gate_o)

            // i*g = 2*i*sg - i ; K*i*g computed in parallel for the scaled state
            const float p   = gi * sg;
            const float ig  = fmaf(2.0f, p, -gi);
            const float ki  = K * gi;
            const float igk = fmaf(K2, p, -ki);

            c  = fmaf(gf, c,  ig);    // c  = f*c  + i*g
            cs = fmaf(gf, cs, igk);   // cs = K*c  (exact same recurrence, pre-scaled)

            // tanh(c) = 2*sigm(2c) - 1, arg already available as cs
            const float rc = rcpf_(1.0f + ex2f_(cs));
            const float tc = fmaf(2.0f, rc, -1.0f);

            h = go * tc;
            op[(t + j) * FF] = h + h;   // forward emits 2*h (store off-chain)
        }
    }
}

extern "C" void kernel_launch(void* const* d_in, const int* in_sizes, int n_in,
                              void* d_out, int out_size) {
    const float*  x    = (const float*) d_in[0];
    const float4* wih  = (const float4*)d_in[1];
    const float4* whh  = (const float4*)d_in[2];
    const float4* bih  = (const float4*)d_in[3];
    const float4* bhh  = (const float4*)d_in[4];
    const float*  h0   = (const float*) d_in[5];
    const float*  c0   = (const float*) d_in[6];
    float*        out  = (float*)d_out;

    // 512 features -> 4 blocks x 128 threads: each warp alone on one SMSP
    // (keeps MUFU issue (10 x rt8 = 80cyc/iter) under the ~100cyc chain).
    lstm_uni_kernel<<<4, 128>>>(x, wih, whh, bih, bhh, h0, c0, out);
}

// round 9
// speedup vs baseline: 1.0037x; 1.0037x over previous
#include <cuda_runtime.h>

// LSTM_Univariate: T=32768 timesteps, F=512 independent scalar LSTM cells.
// One thread per feature; serial recurrence over T with a minimized
// per-iteration dependency chain (~100 cyc). Sigmoid/tanh via
// ex2.approx + rcp.approx (1-2 ulp) with log2(e) pre-folded into weights.

#define TT 32768
#define FF 512
#define PD 8   // x prefetch depth (register ring)

__device__ __forceinline__ float ex2f_(float x) {
    float y; asm("ex2.approx.f32 %0, %1;" : "=f"(y) : "f"(x)); return y;
}
__device__ __forceinline__ float rcpf_(float x) {
    float y; asm("rcp.approx.f32 %0, %1;" : "=f"(y) : "f"(x)); return y;
}

__global__ void __launch_bounds__(128, 1)
lstm_uni_kernel(const float*  __restrict__ x,
                const float4* __restrict__ wih,
                const float4* __restrict__ whh,
                const float4* __restrict__ bih,
                const float4* __restrict__ bhh,
                const float*  __restrict__ h0,
                const float*  __restrict__ c0,
                float*        __restrict__ out)
{
    const int f = blockIdx.x * blockDim.x + threadIdx.x;  // feature id, 0..511

    const float L  = 1.4426950408889634f;   // log2(e)
    const float K  = -2.0f * L;             // scale for tanh args
    const float K2 = 2.0f * K;

    // PyTorch gate order in columns: [i, f, g, o] -> .x .y .z .w
    const float4 wi = wih[f];
    const float4 wh = whh[f];
    const float4 bi = bih[f];
    const float4 bh = bhh[f];

    // sigmoid(z) = rcp(1 + ex2(-L*z));  tanh(z) = 2*rcp(1 + ex2(-2L*z)) - 1.
    // Fold the -L / -2L scales into the per-gate weights & biases.
    const float wii = -L * wi.x,        whi = -L * wh.x,        bii = -L * (bi.x + bh.x);
    const float wff = -L * wi.y,        whf = -L * wh.y,        bff = -L * (bi.y + bh.y);
    const float wgg = -2.0f * L * wi.z, whg = -2.0f * L * wh.z, bgg = -2.0f * L * (bi.z + bh.z);
    const float woo = -L * wi.w,        who = -L * wh.w,        boo = -L * (bi.w + bh.w);

    float h  = h0[f];
    float c  = c0[f];
    float cs = K * c;   // carried pre-scaled cell state: cs == K*c (same recurrence)

    // Prefetch ring: x for iteration t+PD is loaded at iteration t.
    float xb[PD];
#pragma unroll
    for (int j = 0; j < PD; ++j) xb[j] = x[j * FF + f];

    const float* xp = x + f;
    float*       op = out + f;

    for (int t = 0; t < TT; t += PD) {
#pragma unroll
        for (int j = 0; j < PD; ++j) {
            const float xt = xb[j];
            const int tp = t + j + PD;
            if (tp < TT) xb[j] = xp[tp * FF];          // predicated prefetch (off-chain)

            // pre-activations (off the recurrence chain: xt ready PD iters ago)
            const float pi = fmaf(xt, wii, bii);
            const float pf = fmaf(xt, wff, bff);
            const float pg = fmaf(xt, wgg, bgg);
            const float po = fmaf(xt, woo, boo);

            // chain: 1 FFMA to form each (scaled) gate argument
            const float ai = fmaf(h, whi, pi);
            const float af = fmaf(h, whf, pf);
            const float ag = fmaf(h, whg, pg);
            const float ao = fmaf(h, who, po);

            // gate nonlinearities: EX2 -> +1 -> RCP
            const float gi = rcpf_(1.0f + ex2f_(ai));   // i = sigmoid(gate_i)
            const float gf = rcpf_(1.0f + ex2f_(af));   // f = sigmoid(gate_f)
            const float sg = rcpf_(1.0f + ex2f_(ag));   // sigm(2*gate_g); g = 2*sg - 1
            const float go = rcpf_(1.0f + ex2f_(ao));   // o = sigmoid(gate_o)

            // i*g = 2*i*sg - i ; K*i*g computed in parallel for the scaled state
            const float p   = gi * sg;
            const float ig  = fmaf(2.0f, p, -gi);
            const float ki  = K * gi;
            const float igk = fmaf(K2, p, -ki);

            c  = fmaf(gf, c,  ig);    // c  = f*c  + i*g
            cs = fmaf(gf, cs, igk);   // cs = K*c  (exact same recurrence, pre-scaled)

            // tanh(c) = 2*sigm(2c) - 1, arg already available as cs
            const float rc = rcpf_(1.0f + ex2f_(cs));
            const float tc = fmaf(2.0f, rc, -1.0f);

            h = go * tc;
            op[(t + j) * FF] = h + h;   // forward emits 2*h (store off-chain)
        }
    }
}

extern "C" void kernel_launch(void* const* d_in, const int* in_sizes, int n_in,
                              void* d_out, int out_size) {
    const float*  x    = (const float*) d_in[0];
    const float4* wih  = (const float4*)d_in[1];
    const float4* whh  = (const float4*)d_in[2];
    const float4* bih  = (const float4*)d_in[3];
    const float4* bhh  = (const float4*)d_in[4];
    const float*  h0   = (const float*) d_in[5];
    const float*  c0   = (const float*) d_in[6];
    float*        out  = (float*)d_out;

    // 512 features -> 4 blocks x 128 threads: each warp alone on one SMSP
    // (keeps MUFU issue (10 x rt8 = 80cyc/iter) under the ~100cyc chain).
    lstm_uni_kernel<<<4, 128>>>(x, wih, whh, bih, bhh, h0, c0, out);
}